// round 1
// baseline (speedup 1.0000x reference)
#include <cuda_runtime.h>
#include <cstdint>
#include <cstddef>

#define GN 50000
#define GE 1600000
#define GR 4
#define GD 128

// Scratch: device globals (no allocations allowed).
__device__ __align__(16) float g_h[(size_t)GN * GD];           // 25.6 MB
__device__ __align__(16) float g_y[(size_t)GR * GN * GD];      // 102.4 MB

// ---------------------------------------------------------------------------
// Zero the y scratch (float4 stores, grid-stride).
// ---------------------------------------------------------------------------
__global__ void k_zero_y() {
    const size_t total = (size_t)GR * GN * GD / 4;
    float4* p = reinterpret_cast<float4*>(g_y);
    const float4 z = make_float4(0.f, 0.f, 0.f, 0.f);
    for (size_t i = (size_t)blockIdx.x * blockDim.x + threadIdx.x; i < total;
         i += (size_t)gridDim.x * blockDim.x)
        p[i] = z;
}

// ---------------------------------------------------------------------------
// out[n][d] = bias[d]  (float4; D=128 divisible by 4)
// ---------------------------------------------------------------------------
__global__ void k_init_out(float4* __restrict__ out, const float4* __restrict__ bias4) {
    const size_t total = (size_t)GN * GD / 4;
    size_t i = (size_t)blockIdx.x * blockDim.x + threadIdx.x;
    if (i < total) out[i] = bias4[i & (GD / 4 - 1)];
}

// ---------------------------------------------------------------------------
// h = x @ W.  W (128x128 f32 = 64KB) staged in dynamic shared memory.
// One warp per row: lane holds x[row][j*32+lane] in regs, shfl-broadcasts,
// each lane accumulates 4 output columns (d = lane*4 .. lane*4+3).
// ---------------------------------------------------------------------------
__global__ void k_gemm(const float* __restrict__ x, const float* __restrict__ w) {
    extern __shared__ float ws[];  // 128*128 floats
    for (int i = threadIdx.x; i < GD * GD / 4; i += blockDim.x)
        reinterpret_cast<float4*>(ws)[i] = reinterpret_cast<const float4*>(w)[i];
    __syncthreads();

    const int lane   = threadIdx.x & 31;
    const int warp   = (int)((blockIdx.x * blockDim.x + threadIdx.x) >> 5);
    const int nwarps = (int)((gridDim.x * blockDim.x) >> 5);
    const float4* ws4 = reinterpret_cast<const float4*>(ws);

    for (int row = warp; row < GN; row += nwarps) {
        float xr[4];
#pragma unroll
        for (int j = 0; j < 4; j++) xr[j] = x[(size_t)row * GD + j * 32 + lane];

        float4 acc = make_float4(0.f, 0.f, 0.f, 0.f);
#pragma unroll
        for (int j = 0; j < 4; j++) {
#pragma unroll
            for (int kk = 0; kk < 32; kk++) {
                const float xv = __shfl_sync(0xffffffffu, xr[j], kk);
                const float4 wv = ws4[(j * 32 + kk) * 32 + lane];
                acc.x += xv * wv.x;
                acc.y += xv * wv.y;
                acc.z += xv * wv.z;
                acc.w += xv * wv.w;
            }
        }
        reinterpret_cast<float4*>(g_h)[(size_t)row * 32 + lane] = acc;
    }
}

// ---------------------------------------------------------------------------
// Vectorized fire-and-forget scatter-add (sm_90+).
// ---------------------------------------------------------------------------
__device__ __forceinline__ void red_add_v4(float* dst, float4 v) {
    asm volatile("red.global.add.v4.f32 [%0], {%1, %2, %3, %4};"
                 :: "l"(dst), "f"(v.x), "f"(v.y), "f"(v.z), "f"(v.w)
                 : "memory");
}

// ---------------------------------------------------------------------------
// Pass 1 (one r per launch): y_r[rows[e]] += vals[e] * h[cols[e]]
// Warp handles a group of 32 edges: lane t's edge metadata is shfl-broadcast;
// each lane owns a float4 slice (16B) of the 128-dim row.
// rows/cols/vals pointers are pre-offset by r*E on the host.
// ---------------------------------------------------------------------------
__global__ void k_pass1(const int* __restrict__ rows, const int* __restrict__ cols,
                        const float* __restrict__ vals, int r) {
    const int lane = threadIdx.x & 31;
    const int warp = (int)((blockIdx.x * blockDim.x + threadIdx.x) >> 5);
    const int base = warp * 32;
    if (base >= GE) return;

    const int e   = base + lane;
    const int row = rows[e];
    const int col = cols[e];
    const float v = vals[e];

    const float4* hp = reinterpret_cast<const float4*>(g_h);
    float* yb = g_y + (size_t)r * GN * GD;

#pragma unroll 4
    for (int t = 0; t < 32; t++) {
        const int   rw = __shfl_sync(0xffffffffu, row, t);
        const int   cl = __shfl_sync(0xffffffffu, col, t);
        const float vv = __shfl_sync(0xffffffffu, v,   t);
        const float4 hv = hp[cl * 32 + lane];
        float4 o;
        o.x = vv * hv.x; o.y = vv * hv.y; o.z = vv * hv.z; o.w = vv * hv.w;
        red_add_v4(yb + (size_t)rw * GD + lane * 4, o);
    }
}

// ---------------------------------------------------------------------------
// Pass 2 (one r per launch): out[rows[e]] += vals[e] * filt[r*N+cols[e]] * y_r[cols[e]]
// Wavelet filter fused into the gather (saves a full elementwise pass over y).
// ---------------------------------------------------------------------------
__global__ void k_pass2(const int* __restrict__ rows, const int* __restrict__ cols,
                        const float* __restrict__ vals, const float* __restrict__ filt,
                        int r, float* __restrict__ out) {
    const int lane = threadIdx.x & 31;
    const int warp = (int)((blockIdx.x * blockDim.x + threadIdx.x) >> 5);
    const int base = warp * 32;
    if (base >= GE) return;

    const int e   = base + lane;
    const int row = rows[e];
    const int col = cols[e];
    const float v = vals[e] * filt[(size_t)r * GN + col];  // fused filter

    const float4* yp = reinterpret_cast<const float4*>(g_y + (size_t)r * GN * GD);

#pragma unroll 4
    for (int t = 0; t < 32; t++) {
        const int   rw = __shfl_sync(0xffffffffu, row, t);
        const int   cl = __shfl_sync(0xffffffffu, col, t);
        const float vv = __shfl_sync(0xffffffffu, v,   t);
        const float4 yv = yp[cl * 32 + lane];
        float4 o;
        o.x = vv * yv.x; o.y = vv * yv.y; o.z = vv * yv.z; o.w = vv * yv.w;
        red_add_v4(out + (size_t)rw * GD + lane * 4, o);
    }
}

// ---------------------------------------------------------------------------
// Launch. Inputs (metadata order): x, vals, weight, filt, bias, rows, cols.
// ---------------------------------------------------------------------------
extern "C" void kernel_launch(void* const* d_in, const int* in_sizes, int n_in,
                              void* d_out, int out_size) {
    const float* x    = (const float*)d_in[0];
    const float* vals = (const float*)d_in[1];
    const float* w    = (const float*)d_in[2];
    const float* filt = (const float*)d_in[3];
    const float* bias = (const float*)d_in[4];
    const int*   rows = (const int*)d_in[5];
    const int*   cols = (const int*)d_in[6];
    float* out = (float*)d_out;

    (void)in_sizes; (void)n_in; (void)out_size;

    // Allow 64KB dynamic smem for the GEMM's W tile (idempotent, host-side).
    static int smem_set = 0;
    if (!smem_set) {
        cudaFuncSetAttribute(k_gemm, cudaFuncAttributeMaxDynamicSharedMemorySize,
                             GD * GD * (int)sizeof(float));
        smem_set = 1;
    }

    // 1) zero y scratch, init out = bias
    k_zero_y<<<4096, 256>>>();
    k_init_out<<<(GN * GD / 4 + 255) / 256, 256>>>(
        reinterpret_cast<float4*>(out), reinterpret_cast<const float4*>(bias));

    // 2) h = x @ W
    k_gemm<<<1024, 256, GD * GD * sizeof(float)>>>(x, w);

    // 3) pass 1: y_r = D_r @ h   (split by r so h + y_r fits L2)
    const int blocks = GE / 32 / 8;  // warp per 32-edge group, 8 warps/block (exact: E%256==0)
    for (int r = 0; r < GR; r++)
        k_pass1<<<blocks, 256>>>(rows + (size_t)r * GE, cols + (size_t)r * GE,
                                 vals + (size_t)r * GE, r);

    // 4) pass 2: out += D_r @ (filt_r * y_r)
    for (int r = 0; r < GR; r++)
        k_pass2<<<blocks, 256>>>(rows + (size_t)r * GE, cols + (size_t)r * GE,
                                 vals + (size_t)r * GE, filt, r, out);
}